// round 7
// baseline (speedup 1.0000x reference)
#include <cuda_runtime.h>
#include <cuda_bf16.h>
#include <math.h>

// ---------------- problem constants ----------------
#define Bsz 2
#define Sq  256
#define Dm  1024
#define Hh  8
#define HDm 128
#define Ll  16
#define FFd 2048
#define Vv  50257
#define SB  (Sq*Bsz)       // 512 rows, row r = s*Bsz + b  ([S,B,*] layout)
#define SBD (SB*Dm)        // 524288
#define ATT_SCALE 0.08838834764831843f

// ---------------- device scratch (static allocations only) -----------------
__device__ float g_x[SBD];            // current x  [S,B,D]
__device__ float g_q[SBD];            // q proj
__device__ float g_k[Ll*SBD];         // k proj per source
__device__ float g_v[Ll*SBD];         // v proj per source
__device__ float g_scores[Ll*16*Sq*Sq]; // [j][bh][q][k]
__device__ float g_comb[SBD];         // attention combine
__device__ float g_res[SBD];          // residual sum pre-LN
__device__ float g_sp[SBD];           // spikes
__device__ float g_h[SB*FFd];         // ff hidden / snn current (reused)
__device__ float g_lo[Ll*SBD];        // layer outputs

// ---------------- helpers ----------------
__device__ __forceinline__ float4 ldg4_guard(const float* p, int col, int N)
{
    float4 r;
    // vector load only if in-bounds AND 16B-aligned (Vv=50257 is odd!)
    if (col + 3 < N && ((((size_t)p) & 15) == 0)) {
        r = *(const float4*)(p);
    } else {
        r.x = (col+0<N)? p[0]:0.f; r.y = (col+1<N)? p[1]:0.f;
        r.z = (col+2<N)? p[2]:0.f; r.w = (col+3<N)? p[3]:0.f;
    }
    return r;
}

// packed f32x2 FMA: d = a*b + d   (two IEEE fp32 FMAs per instruction)
#define FMA2(d,a,b) asm("fma.rn.f32x2 %0, %1, %2, %0;" : "+l"(d) : "l"(a), "l"(b))

// shared tiles: As is k-major [kk][row] (row pairs pre-packed for f32x2),
// Bd is k-major with every element DUPLICATED: Bd[kk][2n]=Bd[kk][2n+1]=b_n
// so the (b,b) splat operand is a direct LDS, no register packing needed.
#define LDA_S 68    // 64 + 4 pad   (row stride 272B = 16B-aligned)
#define LDB_S 132   // 128 + 4 pad  (row stride 528B = 16B-aligned)

// 8 packed FMAs per kk = 16 scalar FMAs; acc[ip][j] packs rows (2ip,2ip+1)
#define MM2(buf) \
  _Pragma("unroll") \
  for (int kk=0;kk<16;kk++){ \
    ulonglong2 av  = *(const ulonglong2*)&As[buf][kk][ty<<2]; \
    ulonglong2 bv0 = *(const ulonglong2*)&Bd[buf][kk][tx<<3]; \
    ulonglong2 bv1 = *(const ulonglong2*)&Bd[buf][kk][(tx<<3)+4]; \
    FMA2(acc[0][0],av.x,bv0.x); FMA2(acc[0][1],av.x,bv0.y); \
    FMA2(acc[0][2],av.x,bv1.x); FMA2(acc[0][3],av.x,bv1.y); \
    FMA2(acc[1][0],av.y,bv0.x); FMA2(acc[1][1],av.y,bv0.y); \
    FMA2(acc[1][2],av.y,bv1.x); FMA2(acc[1][3],av.y,bv1.y); \
  }

// stage A tile transposed: thread loaded A[m0+arow][k0+acol..+3]
#define STAGE_A(buf, aR) \
  As[buf][acol+0][arow]=aR.x; As[buf][acol+1][arow]=aR.y; \
  As[buf][acol+2][arow]=aR.z; As[buf][acol+3][arow]=aR.w;

// stage B (NN: B[k][n]) duplicated: thread loaded B[k0+brow][n0+bcol..+3]
#define STAGE_B(buf, bR) \
  *(float4*)&Bd[buf][brow][(bcol)<<1]       = make_float4(bR.x,bR.x,bR.y,bR.y); \
  *(float4*)&Bd[buf][brow][((bcol)<<1)+4]   = make_float4(bR.z,bR.z,bR.w,bR.w);

// stage B transposed+dup (NT: B[n][k]): thread loaded Bt[n0+arow][k0+acol..+3]
#define STAGE_BT(buf, kR) \
  { int c2 = arow<<1; \
    Bd[buf][acol+0][c2]=kR.x; Bd[buf][acol+0][c2+1]=kR.x; \
    Bd[buf][acol+1][c2]=kR.y; Bd[buf][acol+1][c2+1]=kR.y; \
    Bd[buf][acol+2][c2]=kR.z; Bd[buf][acol+2][c2+1]=kR.z; \
    Bd[buf][acol+3][c2]=kR.w; Bd[buf][acol+3][c2+1]=kR.w; }

// ---------------- generic tiled SGEMM core: C[M,N] = A[M,K]@B[K,N] ----------
// A row-major lda=K (16B-aligned rows), B row-major ldb=N (any N).
// M multiple of 64, K multiple of 16. 256 threads, 64x64 tile, double buffered.
__device__ __forceinline__ void gemm_core(
    const float* __restrict__ A, const float* __restrict__ Bw,
    const float* __restrict__ bias, const float* __restrict__ res,
    float* __restrict__ C, int N, int K, int relu, int store_T)
{
    __shared__ __align__(16) float As[2][16][LDA_S];
    __shared__ __align__(16) float Bd[2][16][LDB_S];
    const int tid = threadIdx.x;
    const int tx = tid & 15, ty = tid >> 4;
    const int m0 = blockIdx.y << 6, n0 = blockIdx.x << 6;
    const int arow = tid >> 2, acol = (tid & 3) << 2;
    const int brow = tid >> 4, bcol = (tid & 15) << 2;
    unsigned long long acc[2][4] = {{0ull,0ull,0ull,0ull},{0ull,0ull,0ull,0ull}};

    const float* Ap = A + (size_t)(m0 + arow) * K + acol;
    const int nk = K >> 4;
    float4 aR, bR;

    aR = *(const float4*)(Ap);
    bR = ldg4_guard(Bw + (size_t)brow * N + n0 + bcol, n0 + bcol, N);
    STAGE_A(0, aR); STAGE_B(0, bR);
    __syncthreads();

    for (int kt = 1; kt < nk; kt++) {
        aR = *(const float4*)(Ap + kt*16);
        bR = ldg4_guard(Bw + (size_t)(kt*16 + brow) * N + n0 + bcol, n0 + bcol, N);
        const int cb = (kt-1)&1, nb = kt&1;
        MM2(cb);
        STAGE_A(nb, aR); STAGE_B(nb, bR);
        __syncthreads();
    }
    { const int lb = (nk-1)&1; MM2(lb); }

    // epilogue: acc[ip][j] holds rows (m0+ty*4+2ip, +1), col n0+tx*4+j
#pragma unroll
    for (int ip=0; ip<2; ip++){
#pragma unroll
        for (int j=0;j<4;j++){
            int nn = n0 + (tx<<2) + j;
            if (nn >= N) continue;
            float2 f = *(float2*)&acc[ip][j];
            int m = m0 + (ty<<2) + (ip<<1);
#pragma unroll
            for (int rr=0; rr<2; rr++){
                float v = rr ? f.y : f.x;
                int mm = m + rr;
                if (bias) v += bias[nn];
                if (res)  v += res[(size_t)mm*N + nn];
                if (relu) v = fmaxf(v, 0.f);
                if (!store_T) {
                    C[(size_t)mm*N + nn] = v;
                } else {                  // logits: row (s*B+b) -> out[b][s][v]
                    int s = mm >> 1, b = mm & 1;
                    C[(size_t)(b*Sq + s)*N + nn] = v;
                }
            }
        }
    }
}

__global__ void k_gemm(const float* __restrict__ A, const float* __restrict__ Bw,
                       const float* __restrict__ bias, const float* __restrict__ res,
                       float* __restrict__ C, int N, int K, int relu, int store_T)
{
    gemm_core(A, Bw, bias, res, C, N, K, relu, store_T);
}

// ---------------- batched Q/K/V projection: grid.z = 2n+1 ------------------
__global__ void k_kvq(const float* __restrict__ Wq, const float* __restrict__ bq,
                      const float* __restrict__ Wk, const float* __restrict__ bk,
                      const float* __restrict__ Wv, const float* __restrict__ bv,
                      int n)
{
    int z = blockIdx.z;
    const float *A, *W, *bi; float* C;
    if (z == 2*n) { A = g_x; W = Wq; bi = bq; C = g_q; }
    else {
        int isv = (z >= n) ? 1 : 0;
        int j = isv ? z - n : z;
        A = (j == 0) ? g_x : g_lo + (size_t)(j-1)*SBD;
        W = isv ? Wv : Wk;
        bi = isv ? bv : bk;
        C = (isv ? g_v : g_k) + (size_t)j*SBD;
    }
    gemm_core(A, W, bi, nullptr, C, Dm, Dm, 0, 0);
}

// ---------------- embedding + positional encoding ---------------------------
__global__ void k_embed(const int* __restrict__ src, const float* __restrict__ emb)
{
    int idx = blockIdx.x * 256 + threadIdx.x;       // over SBD
    int d = idx & (Dm-1);
    int r = idx >> 10;
    int b = r & 1, s = r >> 1;
    int tok = src[b*Sq + s];
    float v = emb[(size_t)tok*Dm + d] * 32.0f;      // sqrt(1024)
    int de = d & ~1;
    float ang = (float)s * expf((float)de * -0.008994473019508f); // -ln(1e4)/1024
    float pe = (d & 1) ? cosf(ang) : sinf(ang);
    g_x[idx] = v + pe;
}

// ---------------- scores: per (source j, head bh) NT-GEMM (f32x2) -----------
__global__ void k_scores(int n)
{
    __shared__ __align__(16) float As[2][16][LDA_S];
    __shared__ __align__(16) float Bd[2][16][LDB_S];
    const int tid = threadIdx.x;
    const int tx = tid & 15, ty = tid >> 4;
    const int arow = tid >> 2, acol = (tid & 3) << 2;
    const int z = blockIdx.z;                 // z = j*16 + bh
    const int bh = z & 15;
    const int b = bh >> 3, h = bh & 7;
    const int LDX = Bsz * Dm;                 // 2048
    const float* Aq = g_q + b*Dm + h*HDm;
    const float* Bk = g_k + (size_t)(z >> 4)*SBD + b*Dm + h*HDm;
    float* C = g_scores + (size_t)z * Sq * Sq;
    const int m0 = blockIdx.y << 6, n0 = blockIdx.x << 6;
    unsigned long long acc[2][4] = {{0ull,0ull,0ull,0ull},{0ull,0ull,0ull,0ull}};

    const float* Ap = Aq + (size_t)(m0 + arow) * LDX + acol;
    const float* Bp = Bk + (size_t)(n0 + arow) * LDX + acol;
    float4 qR, kR;

    qR = *(const float4*)(Ap);
    kR = *(const float4*)(Bp);
    STAGE_A(0, qR); STAGE_BT(0, kR);
    __syncthreads();

    for (int kt = 1; kt < 8; kt++) {          // HD=128 -> 8 k-tiles
        qR = *(const float4*)(Ap + kt*16);
        kR = *(const float4*)(Bp + kt*16);
        const int cb = (kt-1)&1, nb = kt&1;
        MM2(cb);
        STAGE_A(nb, qR); STAGE_BT(nb, kR);
        __syncthreads();
    }
    MM2(1);

#pragma unroll
    for (int ip=0; ip<2; ip++){
#pragma unroll
        for (int j=0;j<4;j++){
            float2 f = *(float2*)&acc[ip][j];
            int nn = n0 + (tx<<2) + j;
            int m = m0 + (ty<<2) + (ip<<1);
            C[(size_t)m*Sq + nn]     = f.x * ATT_SCALE;
            C[(size_t)(m+1)*Sq + nn] = f.y * ATT_SCALE;
        }
    }
}

// ---------------- softmax over keys x learned layer weight ------------------
__global__ void k_softmax(const float* __restrict__ lw, int n)
{
    int row  = blockIdx.x * 8 + (threadIdx.x >> 5);   // rows = n*16*256
    int lane = threadIdx.x & 31;
    float* p = g_scores + (size_t)row * Sq;
    float x[8];
#pragma unroll
    for (int i=0;i<8;i++) x[i] = p[lane + (i<<5)];
    float mx = x[0];
#pragma unroll
    for (int i=1;i<8;i++) mx = fmaxf(mx, x[i]);
#pragma unroll
    for (int off=16;off>0;off>>=1) mx = fmaxf(mx, __shfl_xor_sync(0xffffffffu, mx, off));
    float sum = 0.f;
#pragma unroll
    for (int i=0;i<8;i++){ x[i] = expf(x[i]-mx); sum += x[i]; }
#pragma unroll
    for (int off=16;off>0;off>>=1) sum += __shfl_xor_sync(0xffffffffu, sum, off);
    int j = row >> 12;                                 // row / (16*256)
    float lm = -1e30f;
    for (int jj=0;jj<n;jj++) lm = fmaxf(lm, lw[jj]);
    float ls = 0.f;
    for (int jj=0;jj<n;jj++) ls += expf(lw[jj]-lm);
    float wj = expf(lw[j]-lm) / ls;
    float sc = wj / sum;
#pragma unroll
    for (int i=0;i<8;i++) p[lane + (i<<5)] = x[i] * sc;
}

// ---------------- comb: per head, sum over sources j of attn_j @ v_j --------
__global__ void k_comb(int n)
{
    __shared__ __align__(16) float As[2][16][LDA_S];
    __shared__ __align__(16) float Bd[2][16][LDB_S];
    const int tid = threadIdx.x;
    const int tx = tid & 15, ty = tid >> 4;
    const int arow = tid >> 2, acol = (tid & 3) << 2;
    const int brow = tid >> 4, bcol = (tid & 15) << 2;
    const int bh = blockIdx.z, b = bh >> 3, h = bh & 7;
    const int m0 = blockIdx.y << 6, n0 = blockIdx.x << 6;   // q tile, d tile
    unsigned long long acc[2][4] = {{0ull,0ull,0ull,0ull},{0ull,0ull,0ull,0ull}};

    for (int j=0;j<n;j++){
        const float* Aj = g_scores + (size_t)(j*16 + bh) * Sq * Sq;   // [q][k] ld=256
        const float* Vj = g_v + (size_t)j*SBD + b*Dm + h*HDm;          // [k][d] ld=2048
        const float* Ap = Aj + (size_t)(m0 + arow) * Sq + acol;
        float4 aR, bR;
        aR = *(const float4*)(Ap);
        bR = *(const float4*)(Vj + (size_t)brow*2048 + n0 + bcol);
        STAGE_A(0, aR); STAGE_B(0, bR);
        __syncthreads();
        for (int kt = 1; kt < 16; kt++) {     // Sq=256 -> 16 k-tiles
            aR = *(const float4*)(Ap + kt*16);
            bR = *(const float4*)(Vj + (size_t)(kt*16+brow)*2048 + n0 + bcol);
            const int cb = (kt-1)&1, nb = kt&1;
            MM2(cb);
            STAGE_A(nb, aR); STAGE_B(nb, bR);
            __syncthreads();
        }
        MM2(1);
        __syncthreads();                      // buffers reused by next source
    }

#pragma unroll
    for (int ip=0; ip<2; ip++){
#pragma unroll
        for (int j=0;j<4;j++){
            float2 f = *(float2*)&acc[ip][j];
            int q = m0 + (ty<<2) + (ip<<1);
            int d = h*HDm + n0 + (tx<<2) + j;
            g_comb[(size_t)(q*Bsz + b)*Dm + d]     = f.x;
            g_comb[(size_t)((q+1)*Bsz + b)*Dm + d] = f.y;
        }
    }
}

// ---------------- layernorm over D of in, write out (and optional copy) -----
__global__ void k_ln(const float* __restrict__ in, const float* __restrict__ g,
                     const float* __restrict__ be, float* __restrict__ out,
                     float* __restrict__ out2)
{
    __shared__ float s1[8], s2[8];
    __shared__ float smean, srstd;
    int r = blockIdx.x, tid = threadIdx.x;
    int lane = tid & 31, wid = tid >> 5;
    const float* row = in + (size_t)r*Dm;
    float v[4], sum = 0.f, sq = 0.f;
#pragma unroll
    for (int i=0;i<4;i++){ v[i] = row[tid + (i<<8)]; sum += v[i]; sq += v[i]*v[i]; }
#pragma unroll
    for (int off=16;off>0;off>>=1){
        sum += __shfl_xor_sync(0xffffffffu, sum, off);
        sq  += __shfl_xor_sync(0xffffffffu, sq,  off);
    }
    if (lane == 0){ s1[wid] = sum; s2[wid] = sq; }
    __syncthreads();
    if (tid == 0){
        float a=0.f, c=0.f;
        for (int i=0;i<8;i++){ a += s1[i]; c += s2[i]; }
        float mean = a * (1.f/1024.f);
        float var  = c * (1.f/1024.f) - mean*mean;
        smean = mean; srstd = rsqrtf(var + 1e-5f);
    }
    __syncthreads();
    float mean = smean, rstd = srstd;
#pragma unroll
    for (int i=0;i<4;i++){
        int d = tid + (i<<8);
        float o = (v[i]-mean)*rstd*g[d] + be[d];
        out[(size_t)r*Dm + d] = o;
        if (out2) out2[(size_t)r*Dm + d] = o;
    }
}

// ---------------- SNN scan: one block per batch, 1024 threads ---------------
__global__ void k_snn(const float* __restrict__ cur, float* __restrict__ sp)
{
    __shared__ float red[32];
    __shared__ float redt;
    int b = blockIdx.x, d = threadIdx.x;
    int lane = d & 31, wid = d >> 5;
    float mem = 0.f, thr = 1.0f;
    float nxt = cur[(size_t)b*Dm + d];               // t = 0 row = (0*B+b)
    for (int t=0;t<Sq;t++){
        float cin = nxt;
        if (t+1 < Sq) nxt = cur[(size_t)((t+1)*Bsz + b)*Dm + d];
        float v = mem;
#pragma unroll
        for (int off=16;off>0;off>>=1) v += __shfl_xor_sync(0xffffffffu, v, off);
        if (lane == 0) red[wid] = v;
        __syncthreads();
        if (wid == 0){
            float u = red[lane];
#pragma unroll
            for (int off=16;off>0;off>>=1) u += __shfl_xor_sync(0xffffffffu, u, off);
            if (lane == 0) redt = u;
        }
        __syncthreads();
        float c = cin - 0.1f * redt;
        mem = 0.9f * mem + c;
        float s = (mem >= thr) ? 1.f : 0.f;
        mem -= s * thr;
        thr = 0.9f * thr + 0.1f * s;
        sp[(size_t)(t*Bsz + b)*Dm + d] = s;
    }
}

// ---------------- host orchestration ----------------------------------------
extern "C" void kernel_launch(void* const* d_in, const int* in_sizes, int n_in,
                              void* d_out, int out_size)
{
    const int*   src  = (const int*)  d_in[0];
    const float* emb  = (const float*)d_in[1];
    const float* Wq   = (const float*)d_in[2];
    const float* bq   = (const float*)d_in[3];
    const float* Wk   = (const float*)d_in[4];
    const float* bk   = (const float*)d_in[5];
    const float* Wv   = (const float*)d_in[6];
    const float* bv   = (const float*)d_in[7];
    const float* Wo   = (const float*)d_in[8];
    const float* bo   = (const float*)d_in[9];
    const float* layer_w = (const float*)d_in[10];
    const float* Wsnn = (const float*)d_in[11];
    const float* bsnn = (const float*)d_in[12];
    const float* W1   = (const float*)d_in[13];
    const float* b1   = (const float*)d_in[14];
    const float* W2   = (const float*)d_in[15];
    const float* b2   = (const float*)d_in[16];
    const float* g1   = (const float*)d_in[17];
    const float* be1  = (const float*)d_in[18];
    const float* g2   = (const float*)d_in[19];
    const float* be2  = (const float*)d_in[20];
    const float* Wout = (const float*)d_in[21];
    const float* bout = (const float*)d_in[22];
    float* out = (float*)d_out;

    float *px, *pcomb, *pres, *psp, *ph, *plo;
    cudaGetSymbolAddress((void**)&px,    g_x);
    cudaGetSymbolAddress((void**)&pcomb, g_comb);
    cudaGetSymbolAddress((void**)&pres,  g_res);
    cudaGetSymbolAddress((void**)&psp,   g_sp);
    cudaGetSymbolAddress((void**)&ph,    g_h);
    cudaGetSymbolAddress((void**)&plo,   g_lo);

    k_embed<<<SBD/256, 256>>>(src, emb);

    for (int l=0; l<Ll; l++){
        int n = l + 1;
        const float* Wql = Wq + (size_t)l*Dm*Dm;
        const float* Wkl = Wk + (size_t)l*Dm*Dm;
        const float* Wvl = Wv + (size_t)l*Dm*Dm;

        // Q + n*K + n*V projections, batched over grid.z
        k_kvq<<<dim3(16,8,2*n+1), 256>>>(Wql, bq + l*Dm, Wkl, bk + l*Dm,
                                         Wvl, bv + l*Dm, n);
        // attention scores, per (source, head)
        k_scores<<<dim3(4,4,n*16), 256>>>(n);
        // softmax over keys x layer-weight softmax
        k_softmax<<<n*16*Sq/8, 256>>>(layer_w + l*(Ll+1), n);
        // combine over (k, source)
        k_comb<<<dim3(2,4,16), 256>>>(n);
        // output projection + residual
        k_gemm<<<dim3(16,8), 256>>>(pcomb, Wo + (size_t)l*Dm*Dm, bo + l*Dm,
                                    px, pres, Dm, Dm, 0, 0);
        // LN1 -> new x
        k_ln<<<SB, 256>>>(pres, g1 + l*Dm, be1 + l*Dm, px, (float*)nullptr);
        // SNN input current
        k_gemm<<<dim3(16,8), 256>>>(px, Wsnn + (size_t)l*Dm*Dm, bsnn + l*Dm,
                                    (const float*)nullptr, ph, Dm, Dm, 0, 0);
        // membrane scan -> spikes
        k_snn<<<Bsz, 1024>>>(ph, psp);
        // FF1 (relu)
        k_gemm<<<dim3(32,8), 256>>>(psp, W1 + (size_t)l*Dm*FFd, b1 + l*FFd,
                                    (const float*)nullptr, ph, FFd, Dm, 1, 0);
        // FF2 + residual
        k_gemm<<<dim3(16,8), 256>>>(ph, W2 + (size_t)l*FFd*Dm, b2 + l*Dm,
                                    px, pres, Dm, FFd, 0, 0);
        // LN2 -> new x, also store as this layer's output
        k_ln<<<SB, 256>>>(pres, g2 + l*Dm, be2 + l*Dm, px, plo + (size_t)l*SBD);
    }

    // final logits with transposed store into [B,S,V]
    k_gemm<<<dim3((Vv+63)/64, 8), 256>>>(px, Wout, bout, (const float*)nullptr,
                                         out, Vv, Dm, 0, 1);
}

// round 9
// speedup vs baseline: 2.1734x; 2.1734x over previous
#include <cuda_runtime.h>
#include <cuda_bf16.h>
#include <math.h>

// ---------------- problem constants ----------------
#define Bsz 2
#define Sq  256
#define Dm  1024
#define Hh  8
#define HDm 128
#define Ll  16
#define FFd 2048
#define Vv  50257
#define SB  (Sq*Bsz)       // 512 rows, row r = s*Bsz + b  ([S,B,*] layout)
#define SBD (SB*Dm)        // 524288
#define ATT_SCALE 0.08838834764831843f

// ---------------- device scratch (static allocations only) -----------------
__device__ float g_x[SBD];            // current x  [S,B,D]
__device__ float g_q[SBD];            // q proj
__device__ float g_k[Ll*SBD];         // k proj per source
__device__ float g_v[Ll*SBD];         // v proj per source
__device__ float g_scores[Ll*16*Sq*Sq]; // [j][bh][q][k]
__device__ float g_comb[SBD];         // attention combine
__device__ float g_res[SBD];          // residual sum pre-LN
__device__ float g_sp[SBD];           // spikes
__device__ float g_h[SB*FFd];         // ff hidden / snn current (reused)
__device__ float g_lo[Ll*SBD];        // layer outputs

// ---------------- helpers ----------------
__device__ __forceinline__ float4 ldg4_guard(const float* p, int col, int N)
{
    float4 r;
    // vector load only if in-bounds AND 16B-aligned (Vv=50257 is odd!)
    if (col + 3 < N && ((((size_t)p) & 15) == 0)) {
        r = *(const float4*)(p);
    } else {
        r.x = (col+0<N)? p[0]:0.f; r.y = (col+1<N)? p[1]:0.f;
        r.z = (col+2<N)? p[2]:0.f; r.w = (col+3<N)? p[3]:0.f;
    }
    return r;
}

// k-major shared tiles: Ts[kk][row], row stride 68 floats (272B, 16B-aligned)
#define LDK 68

// inner product step: one LDS.128 per fragment, 16 scalar FFMA
#define MM16F(Abuf, Bbuf) \
  _Pragma("unroll") \
  for (int kk=0;kk<16;kk++){ \
    float4 a4 = *(const float4*)&Abuf[kk][ty<<2]; \
    float4 b4 = *(const float4*)&Bbuf[kk][tx<<2]; \
    acc[0][0]=fmaf(a4.x,b4.x,acc[0][0]); acc[0][1]=fmaf(a4.x,b4.y,acc[0][1]); \
    acc[0][2]=fmaf(a4.x,b4.z,acc[0][2]); acc[0][3]=fmaf(a4.x,b4.w,acc[0][3]); \
    acc[1][0]=fmaf(a4.y,b4.x,acc[1][0]); acc[1][1]=fmaf(a4.y,b4.y,acc[1][1]); \
    acc[1][2]=fmaf(a4.y,b4.z,acc[1][2]); acc[1][3]=fmaf(a4.y,b4.w,acc[1][3]); \
    acc[2][0]=fmaf(a4.z,b4.x,acc[2][0]); acc[2][1]=fmaf(a4.z,b4.y,acc[2][1]); \
    acc[2][2]=fmaf(a4.z,b4.z,acc[2][2]); acc[2][3]=fmaf(a4.z,b4.w,acc[2][3]); \
    acc[3][0]=fmaf(a4.w,b4.x,acc[3][0]); acc[3][1]=fmaf(a4.w,b4.y,acc[3][1]); \
    acc[3][2]=fmaf(a4.w,b4.z,acc[3][2]); acc[3][3]=fmaf(a4.w,b4.w,acc[3][3]); \
  }

// stage a row-major-loaded float4 (row arow, cols acol..acol+3) transposed
// into a k-major tile: T[acol+i][arow]
#define STAGE_T(T, buf, v) \
  T[buf][acol+0][arow]=v.x; T[buf][acol+1][arow]=v.y; \
  T[buf][acol+2][arow]=v.z; T[buf][acol+3][arow]=v.w;

// stage a k-row-loaded float4 (k row brow, cols bcol..+3) straight in
#define STAGE_K(T, buf, v) *(float4*)&T[buf][brow][bcol] = v;

// ---------------- generic tiled SGEMM core: C[M,N] = A[M,K]@B[K,N] ----------
// A row-major lda=K (16B-aligned rows), B row-major ldb=N (any N).
// M multiple of 64, K multiple of 16. 256 threads, 64x64 tile, double buffered.
__device__ __forceinline__ void gemm_core(
    const float* __restrict__ A, const float* __restrict__ Bw,
    const float* __restrict__ bias, const float* __restrict__ res,
    float* __restrict__ C, int N, int K, int relu, int store_T)
{
    __shared__ __align__(16) float As[2][16][LDK];
    __shared__ __align__(16) float Bs[2][16][LDK];
    const int tid = threadIdx.x;
    const int tx = tid & 15, ty = tid >> 4;
    const int m0 = blockIdx.y << 6, n0 = blockIdx.x << 6;
    const int arow = tid >> 2, acol = (tid & 3) << 2;
    const int brow = tid >> 4, bcol = (tid & 15) << 2;
    float acc[4][4];
#pragma unroll
    for (int i=0;i<4;i++)
#pragma unroll
        for (int j=0;j<4;j++) acc[i][j]=0.f;

    const float* Ap = A + (size_t)(m0 + arow) * K + acol;
    const int nk = K >> 4;
    float4 aR, bR;

    aR = *(const float4*)(Ap);
    bR = ldg4_guard(Bw + (size_t)brow * N + n0 + bcol, n0 + bcol, N);
    STAGE_T(As, 0, aR); STAGE_K(Bs, 0, bR);
    __syncthreads();

    for (int kt = 1; kt < nk; kt++) {
        aR = *(const float4*)(Ap + kt*16);
        bR = ldg4_guard(Bw + (size_t)(kt*16 + brow) * N + n0 + bcol, n0 + bcol, N);
        const int cb = (kt-1)&1, nb = kt&1;
        MM16F(As[cb], Bs[cb]);
        STAGE_T(As, nb, aR); STAGE_K(Bs, nb, bR);
        __syncthreads();
    }
    { const int lb = (nk-1)&1; MM16F(As[lb], Bs[lb]); }

    // epilogue: acc[i][j] -> row m0+ty*4+i, col n0+tx*4+j
#pragma unroll
    for (int i=0;i<4;i++){
        int m = m0 + (ty<<2) + i;
#pragma unroll
        for (int j=0;j<4;j++){
            int nn = n0 + (tx<<2) + j;
            if (nn >= N) continue;
            float v = acc[i][j];
            if (bias) v += bias[nn];
            if (res)  v += res[(size_t)m*N + nn];
            if (relu) v = fmaxf(v, 0.f);
            if (!store_T) {
                C[(size_t)m*N + nn] = v;
            } else {                      // logits: row (s*B+b) -> out[b][s][v]
                int s = m >> 1, b = m & 1;
                C[(size_t)(b*Sq + s)*N + nn] = v;
            }
        }
    }
}

__global__ void k_gemm(const float* __restrict__ A, const float* __restrict__ Bw,
                       const float* __restrict__ bias, const float* __restrict__ res,
                       float* __restrict__ C, int N, int K, int relu, int store_T)
{
    gemm_core(A, Bw, bias, res, C, N, K, relu, store_T);
}

// ---------------- batched Q/K/V projection: grid.z = 2n+1 ------------------
__global__ void k_kvq(const float* __restrict__ Wq, const float* __restrict__ bq,
                      const float* __restrict__ Wk, const float* __restrict__ bk,
                      const float* __restrict__ Wv, const float* __restrict__ bv,
                      int n)
{
    int z = blockIdx.z;
    const float *A, *W, *bi; float* C;
    if (z == 2*n) { A = g_x; W = Wq; bi = bq; C = g_q; }
    else {
        int isv = (z >= n) ? 1 : 0;
        int j = isv ? z - n : z;
        A = (j == 0) ? g_x : g_lo + (size_t)(j-1)*SBD;
        W = isv ? Wv : Wk;
        bi = isv ? bv : bk;
        C = (isv ? g_v : g_k) + (size_t)j*SBD;
    }
    gemm_core(A, W, bi, nullptr, C, Dm, Dm, 0, 0);
}

// ---------------- embedding + positional encoding ---------------------------
__global__ void k_embed(const int* __restrict__ src, const float* __restrict__ emb)
{
    int idx = blockIdx.x * 256 + threadIdx.x;       // over SBD
    int d = idx & (Dm-1);
    int r = idx >> 10;
    int b = r & 1, s = r >> 1;
    int tok = src[b*Sq + s];
    float v = emb[(size_t)tok*Dm + d] * 32.0f;      // sqrt(1024)
    int de = d & ~1;
    float ang = (float)s * expf((float)de * -0.008994473019508f); // -ln(1e4)/1024
    float pe = (d & 1) ? cosf(ang) : sinf(ang);
    g_x[idx] = v + pe;
}

// ---------------- scores: per (source j, head bh) NT-GEMM -------------------
__global__ void k_scores(int n)
{
    __shared__ __align__(16) float Qs[2][16][LDK];
    __shared__ __align__(16) float Ks[2][16][LDK];
    const int tid = threadIdx.x;
    const int tx = tid & 15, ty = tid >> 4;
    const int arow = tid >> 2, acol = (tid & 3) << 2;
    const int z = blockIdx.z;                 // z = j*16 + bh
    const int bh = z & 15;
    const int b = bh >> 3, h = bh & 7;
    const int LDX = Bsz * Dm;                 // 2048
    const float* Aq = g_q + b*Dm + h*HDm;
    const float* Bk = g_k + (size_t)(z >> 4)*SBD + b*Dm + h*HDm;
    float* C = g_scores + (size_t)z * Sq * Sq;
    const int m0 = blockIdx.y << 6, n0 = blockIdx.x << 6;
    float acc[4][4];
#pragma unroll
    for (int i=0;i<4;i++)
#pragma unroll
        for (int j=0;j<4;j++) acc[i][j]=0.f;

    const float* Ap = Aq + (size_t)(m0 + arow) * LDX + acol;
    const float* Bp = Bk + (size_t)(n0 + arow) * LDX + acol;
    float4 qR, kR;

    qR = *(const float4*)(Ap);
    kR = *(const float4*)(Bp);
    STAGE_T(Qs, 0, qR); STAGE_T(Ks, 0, kR);
    __syncthreads();

    for (int kt = 1; kt < 8; kt++) {          // HD=128 -> 8 k-tiles
        qR = *(const float4*)(Ap + kt*16);
        kR = *(const float4*)(Bp + kt*16);
        const int cb = (kt-1)&1, nb = kt&1;
        MM16F(Qs[cb], Ks[cb]);
        STAGE_T(Qs, nb, qR); STAGE_T(Ks, nb, kR);
        __syncthreads();
    }
    MM16F(Qs[1], Ks[1]);

#pragma unroll
    for (int i=0;i<4;i++){
        int m = m0 + (ty<<2) + i;
#pragma unroll
        for (int j=0;j<4;j++){
            int nn = n0 + (tx<<2) + j;
            C[(size_t)m*Sq + nn] = acc[i][j] * ATT_SCALE;
        }
    }
}

// ---------------- softmax over keys x learned layer weight ------------------
__global__ void k_softmax(const float* __restrict__ lw, int n)
{
    int row  = blockIdx.x * 8 + (threadIdx.x >> 5);   // rows = n*16*256
    int lane = threadIdx.x & 31;
    float* p = g_scores + (size_t)row * Sq;
    float x[8];
#pragma unroll
    for (int i=0;i<8;i++) x[i] = p[lane + (i<<5)];
    float mx = x[0];
#pragma unroll
    for (int i=1;i<8;i++) mx = fmaxf(mx, x[i]);
#pragma unroll
    for (int off=16;off>0;off>>=1) mx = fmaxf(mx, __shfl_xor_sync(0xffffffffu, mx, off));
    float sum = 0.f;
#pragma unroll
    for (int i=0;i<8;i++){ x[i] = expf(x[i]-mx); sum += x[i]; }
#pragma unroll
    for (int off=16;off>0;off>>=1) sum += __shfl_xor_sync(0xffffffffu, sum, off);
    int j = row >> 12;                                 // row / (16*256)
    float lm = -1e30f;
    for (int jj=0;jj<n;jj++) lm = fmaxf(lm, lw[jj]);
    float ls = 0.f;
    for (int jj=0;jj<n;jj++) ls += expf(lw[jj]-lm);
    float wj = expf(lw[j]-lm) / ls;
    float sc = wj / sum;
#pragma unroll
    for (int i=0;i<8;i++) p[lane + (i<<5)] = x[i] * sc;
}

// ---------------- comb: per head, sum over sources j of attn_j @ v_j --------
__global__ void k_comb(int n)
{
    __shared__ __align__(16) float As[2][16][LDK];
    __shared__ __align__(16) float Bs[2][16][LDK];
    const int tid = threadIdx.x;
    const int tx = tid & 15, ty = tid >> 4;
    const int arow = tid >> 2, acol = (tid & 3) << 2;
    const int brow = tid >> 4, bcol = (tid & 15) << 2;
    const int bh = blockIdx.z, b = bh >> 3, h = bh & 7;
    const int m0 = blockIdx.y << 6, n0 = blockIdx.x << 6;   // q tile, d tile
    float acc[4][4];
#pragma unroll
    for (int i=0;i<4;i++)
#pragma unroll
        for (int j=0;j<4;j++) acc[i][j]=0.f;

    for (int j=0;j<n;j++){
        const float* Aj = g_scores + (size_t)(j*16 + bh) * Sq * Sq;   // [q][k] ld=256
        const float* Vj = g_v + (size_t)j*SBD + b*Dm + h*HDm;          // [k][d] ld=2048
        const float* Ap = Aj + (size_t)(m0 + arow) * Sq + acol;
        float4 aR, bR;
        aR = *(const float4*)(Ap);
        bR = *(const float4*)(Vj + (size_t)brow*2048 + n0 + bcol);
        STAGE_T(As, 0, aR); STAGE_K(Bs, 0, bR);
        __syncthreads();
        for (int kt = 1; kt < 16; kt++) {     // Sq=256 -> 16 k-tiles
            aR = *(const float4*)(Ap + kt*16);
            bR = *(const float4*)(Vj + (size_t)(kt*16+brow)*2048 + n0 + bcol);
            const int cb = (kt-1)&1, nb = kt&1;
            MM16F(As[cb], Bs[cb]);
            STAGE_T(As, nb, aR); STAGE_K(Bs, nb, bR);
            __syncthreads();
        }
        MM16F(As[1], Bs[1]);
        __syncthreads();                      // buffers reused by next source
    }

#pragma unroll
    for (int i=0;i<4;i++){
        int q = m0 + (ty<<2) + i;
        int r = q*Bsz + b;
#pragma unroll
        for (int j=0;j<4;j++){
            int d = h*HDm + n0 + (tx<<2) + j;
            g_comb[(size_t)r*Dm + d] = acc[i][j];
        }
    }
}

// ---------------- layernorm over D of in, write out (and optional copy) -----
__global__ void k_ln(const float* __restrict__ in, const float* __restrict__ g,
                     const float* __restrict__ be, float* __restrict__ out,
                     float* __restrict__ out2)
{
    __shared__ float s1[8], s2[8];
    __shared__ float smean, srstd;
    int r = blockIdx.x, tid = threadIdx.x;
    int lane = tid & 31, wid = tid >> 5;
    const float* row = in + (size_t)r*Dm;
    float v[4], sum = 0.f, sq = 0.f;
#pragma unroll
    for (int i=0;i<4;i++){ v[i] = row[tid + (i<<8)]; sum += v[i]; sq += v[i]*v[i]; }
#pragma unroll
    for (int off=16;off>0;off>>=1){
        sum += __shfl_xor_sync(0xffffffffu, sum, off);
        sq  += __shfl_xor_sync(0xffffffffu, sq,  off);
    }
    if (lane == 0){ s1[wid] = sum; s2[wid] = sq; }
    __syncthreads();
    if (tid == 0){
        float a=0.f, c=0.f;
        for (int i=0;i<8;i++){ a += s1[i]; c += s2[i]; }
        float mean = a * (1.f/1024.f);
        float var  = c * (1.f/1024.f) - mean*mean;
        smean = mean; srstd = rsqrtf(var + 1e-5f);
    }
    __syncthreads();
    float mean = smean, rstd = srstd;
#pragma unroll
    for (int i=0;i<4;i++){
        int d = tid + (i<<8);
        float o = (v[i]-mean)*rstd*g[d] + be[d];
        out[(size_t)r*Dm + d] = o;
        if (out2) out2[(size_t)r*Dm + d] = o;
    }
}

// ---------------- SNN scan: one block per batch, 1024 threads ---------------
__global__ void k_snn(const float* __restrict__ cur, float* __restrict__ sp)
{
    __shared__ float red[32];
    __shared__ float redt;
    int b = blockIdx.x, d = threadIdx.x;
    int lane = d & 31, wid = d >> 5;
    float mem = 0.f, thr = 1.0f;
    float nxt = cur[(size_t)b*Dm + d];               // t = 0 row = (0*B+b)
    for (int t=0;t<Sq;t++){
        float cin = nxt;
        if (t+1 < Sq) nxt = cur[(size_t)((t+1)*Bsz + b)*Dm + d];
        float v = mem;
#pragma unroll
        for (int off=16;off>0;off>>=1) v += __shfl_xor_sync(0xffffffffu, v, off);
        if (lane == 0) red[wid] = v;
        __syncthreads();
        if (wid == 0){
            float u = red[lane];
#pragma unroll
            for (int off=16;off>0;off>>=1) u += __shfl_xor_sync(0xffffffffu, u, off);
            if (lane == 0) redt = u;
        }
        __syncthreads();
        float c = cin - 0.1f * redt;
        mem = 0.9f * mem + c;
        float s = (mem >= thr) ? 1.f : 0.f;
        mem -= s * thr;
        thr = 0.9f * thr + 0.1f * s;
        sp[(size_t)(t*Bsz + b)*Dm + d] = s;
    }
}

// ---------------- host orchestration ----------------------------------------
extern "C" void kernel_launch(void* const* d_in, const int* in_sizes, int n_in,
                              void* d_out, int out_size)
{
    const int*   src  = (const int*)  d_in[0];
    const float* emb  = (const float*)d_in[1];
    const float* Wq   = (const float*)d_in[2];
    const float* bq   = (const float*)d_in[3];
    const float* Wk   = (const float*)d_in[4];
    const float* bk   = (const float*)d_in[5];
    const float* Wv   = (const float*)d_in[6];
    const float* bv   = (const float*)d_in[7];
    const float* Wo   = (const float*)d_in[8];
    const float* bo   = (const float*)d_in[9];
    const float* layer_w = (const float*)d_in[10];
    const float* Wsnn = (const float*)d_in[11];
    const float* bsnn = (const float*)d_in[12];
    const float* W1   = (const float*)d_in[13];
    const float* b1   = (const float*)d_in[14];
    const float* W2   = (const float*)d_in[15];
    const float* b2   = (const float*)d_in[16];
    const float* g1   = (const float*)d_in[17];
    const float* be1  = (const float*)d_in[18];
    const float* g2   = (const float*)d_in[19];
    const float* be2  = (const float*)d_in[20];
    const float* Wout = (const float*)d_in[21];
    const float* bout = (const float*)d_in[22];
    float* out = (float*)d_out;

    float *px, *pcomb, *pres, *psp, *ph, *plo;
    cudaGetSymbolAddress((void**)&px,    g_x);
    cudaGetSymbolAddress((void**)&pcomb, g_comb);
    cudaGetSymbolAddress((void**)&pres,  g_res);
    cudaGetSymbolAddress((void**)&psp,   g_sp);
    cudaGetSymbolAddress((void**)&ph,    g_h);
    cudaGetSymbolAddress((void**)&plo,   g_lo);

    k_embed<<<SBD/256, 256>>>(src, emb);

    for (int l=0; l<Ll; l++){
        int n = l + 1;
        const float* Wql = Wq + (size_t)l*Dm*Dm;
        const float* Wkl = Wk + (size_t)l*Dm*Dm;
        const float* Wvl = Wv + (size_t)l*Dm*Dm;

        // Q + n*K + n*V projections, batched over grid.z
        k_kvq<<<dim3(16,8,2*n+1), 256>>>(Wql, bq + l*Dm, Wkl, bk + l*Dm,
                                         Wvl, bv + l*Dm, n);
        // attention scores, per (source, head)
        k_scores<<<dim3(4,4,n*16), 256>>>(n);
        // softmax over keys x layer-weight softmax
        k_softmax<<<n*16*Sq/8, 256>>>(layer_w + l*(Ll+1), n);
        // combine over (k, source)
        k_comb<<<dim3(2,4,16), 256>>>(n);
        // output projection + residual
        k_gemm<<<dim3(16,8), 256>>>(pcomb, Wo + (size_t)l*Dm*Dm, bo + l*Dm,
                                    px, pres, Dm, Dm, 0, 0);
        // LN1 -> new x
        k_ln<<<SB, 256>>>(pres, g1 + l*Dm, be1 + l*Dm, px, (float*)nullptr);
        // SNN input current
        k_gemm<<<dim3(16,8), 256>>>(px, Wsnn + (size_t)l*Dm*Dm, bsnn + l*Dm,
                                    (const float*)nullptr, ph, Dm, Dm, 0, 0);
        // membrane scan -> spikes
        k_snn<<<Bsz, 1024>>>(ph, psp);
        // FF1 (relu)
        k_gemm<<<dim3(32,8), 256>>>(psp, W1 + (size_t)l*Dm*FFd, b1 + l*FFd,
                                    (const float*)nullptr, ph, FFd, Dm, 1, 0);
        // FF2 + residual
        k_gemm<<<dim3(16,8), 256>>>(ph, W2 + (size_t)l*FFd*Dm, b2 + l*Dm,
                                    px, pres, Dm, FFd, 0, 0);
        // LN2 -> new x, also store as this layer's output
        k_ln<<<SB, 256>>>(pres, g2 + l*Dm, be2 + l*Dm, px, plo + (size_t)l*SBD);
    }

    // final logits with transposed store into [B,S,V]
    k_gemm<<<dim3((Vv+63)/64, 8), 256>>>(px, Wout, bout, (const float*)nullptr,
                                         out, Vv, Dm, 0, 1);
}

// round 12
// speedup vs baseline: 2.4055x; 1.1068x over previous
#include <cuda_runtime.h>
#include <cuda_bf16.h>
#include <math.h>

// ---------------- problem constants ----------------
#define Bsz 2
#define Sq  256
#define Dm  1024
#define Hh  8
#define HDm 128
#define Ll  16
#define FFd 2048
#define Vv  50257
#define SB  (Sq*Bsz)       // 512 rows, row r = s*Bsz + b  ([S,B,*] layout)
#define SBD (SB*Dm)        // 524288
#define ATT_SCALE 0.08838834764831843f

// ---------------- device scratch (static allocations only) -----------------
__device__ float g_x[SBD];            // current x  [S,B,D]
__device__ float g_q[SBD];            // q proj
__device__ float g_k[Ll*SBD];         // k proj per (deduped) source
__device__ float g_v[Ll*SBD];         // v proj per source
__device__ float g_scores[Ll*16*Sq*Sq]; // [j][bh][q][k]
__device__ float g_comb[SBD];         // attention combine
__device__ float g_res[SBD];          // partial / residual sum pre-LN
__device__ float g_p2[SBD];           // second split-K partial
__device__ float g_sp[SBD];           // spikes
__device__ float g_h[SB*FFd];         // ff hidden / snn current (reused)
__device__ float g_lo[Ll*SBD];        // layer outputs

// ---------------- helpers ----------------
__device__ __forceinline__ float4 ldg4_guard(const float* p, int col, int N)
{
    float4 r;
    // vector load only if in-bounds AND 16B-aligned (Vv=50257 is odd!)
    if (col + 3 < N && ((((size_t)p) & 15) == 0)) {
        r = *(const float4*)(p);
    } else {
        r.x = (col+0<N)? p[0]:0.f; r.y = (col+1<N)? p[1]:0.f;
        r.z = (col+2<N)? p[2]:0.f; r.w = (col+3<N)? p[3]:0.f;
    }
    return r;
}

// k-major shared tiles: Ts[kk][row], row stride 68 floats (272B, 16B-aligned)
#define LDK 68

// inner product step: one LDS.128 per fragment, 16 scalar FFMA
#define MM16F(Abuf, Bbuf) \
  _Pragma("unroll") \
  for (int kk=0;kk<16;kk++){ \
    float4 a4 = *(const float4*)&Abuf[kk][ty<<2]; \
    float4 b4 = *(const float4*)&Bbuf[kk][tx<<2]; \
    acc[0][0]=fmaf(a4.x,b4.x,acc[0][0]); acc[0][1]=fmaf(a4.x,b4.y,acc[0][1]); \
    acc[0][2]=fmaf(a4.x,b4.z,acc[0][2]); acc[0][3]=fmaf(a4.x,b4.w,acc[0][3]); \
    acc[1][0]=fmaf(a4.y,b4.x,acc[1][0]); acc[1][1]=fmaf(a4.y,b4.y,acc[1][1]); \
    acc[1][2]=fmaf(a4.y,b4.z,acc[1][2]); acc[1][3]=fmaf(a4.y,b4.w,acc[1][3]); \
    acc[2][0]=fmaf(a4.z,b4.x,acc[2][0]); acc[2][1]=fmaf(a4.z,b4.y,acc[2][1]); \
    acc[2][2]=fmaf(a4.z,b4.z,acc[2][2]); acc[2][3]=fmaf(a4.z,b4.w,acc[2][3]); \
    acc[3][0]=fmaf(a4.w,b4.x,acc[3][0]); acc[3][1]=fmaf(a4.w,b4.y,acc[3][1]); \
    acc[3][2]=fmaf(a4.w,b4.z,acc[3][2]); acc[3][3]=fmaf(a4.w,b4.w,acc[3][3]); \
  }

// stage a row-major-loaded float4 (row arow, cols acol..acol+3) transposed
#define STAGE_T(T, buf, v) \
  T[buf][acol+0][arow]=v.x; T[buf][acol+1][arow]=v.y; \
  T[buf][acol+2][arow]=v.z; T[buf][acol+3][arow]=v.w;

// stage a k-row-loaded float4 (k row brow, cols bcol..+3) straight in
#define STAGE_K(T, buf, v) *(float4*)&T[buf][brow][bcol] = v;

// ---------------- generic tiled SGEMM core: C[M,N] = A[M,Kred]@B[Kred,N] ----
// A row-major with leading dim lda; B row-major ldb=N (any N).
// M multiple of 64, Kred multiple of 16. 256 threads, 64x64 tile, dbl buffered.
__device__ __forceinline__ void gemm_core(
    const float* __restrict__ A, int lda, const float* __restrict__ Bw,
    const float* __restrict__ bias, const float* __restrict__ res,
    float* __restrict__ C, int N, int Kred, int relu, int store_T)
{
    __shared__ __align__(16) float As[2][16][LDK];
    __shared__ __align__(16) float Bs[2][16][LDK];
    const int tid = threadIdx.x;
    const int tx = tid & 15, ty = tid >> 4;
    const int m0 = blockIdx.y << 6, n0 = blockIdx.x << 6;
    const int arow = tid >> 2, acol = (tid & 3) << 2;
    const int brow = tid >> 4, bcol = (tid & 15) << 2;
    float acc[4][4];
#pragma unroll
    for (int i=0;i<4;i++)
#pragma unroll
        for (int j=0;j<4;j++) acc[i][j]=0.f;

    const float* Ap = A + (size_t)(m0 + arow) * lda + acol;
    const int nk = Kred >> 4;
    float4 aR, bR;

    aR = *(const float4*)(Ap);
    bR = ldg4_guard(Bw + (size_t)brow * N + n0 + bcol, n0 + bcol, N);
    STAGE_T(As, 0, aR); STAGE_K(Bs, 0, bR);
    __syncthreads();

    for (int kt = 1; kt < nk; kt++) {
        aR = *(const float4*)(Ap + kt*16);
        bR = ldg4_guard(Bw + (size_t)(kt*16 + brow) * N + n0 + bcol, n0 + bcol, N);
        const int cb = (kt-1)&1, nb = kt&1;
        MM16F(As[cb], Bs[cb]);
        STAGE_T(As, nb, aR); STAGE_K(Bs, nb, bR);
        __syncthreads();
    }
    { const int lb = (nk-1)&1; MM16F(As[lb], Bs[lb]); }

#pragma unroll
    for (int i=0;i<4;i++){
        int m = m0 + (ty<<2) + i;
#pragma unroll
        for (int j=0;j<4;j++){
            int nn = n0 + (tx<<2) + j;
            if (nn >= N) continue;
            float v = acc[i][j];
            if (bias) v += bias[nn];
            if (res)  v += res[(size_t)m*N + nn];
            if (relu) v = fmaxf(v, 0.f);
            if (!store_T) {
                C[(size_t)m*N + nn] = v;
            } else {                      // logits: row (s*B+b) -> out[b][s][v]
                int s = m >> 1, b = m & 1;
                C[(size_t)(b*Sq + s)*N + nn] = v;
            }
        }
    }
}

__global__ void k_gemm(const float* __restrict__ A, const float* __restrict__ Bw,
                       const float* __restrict__ bias, const float* __restrict__ res,
                       float* __restrict__ C, int N, int K, int relu, int store_T)
{
    gemm_core(A, K, Bw, bias, res, C, N, K, relu, store_T);
}

// split-K=2: z=0 does k in [0,K/2) (+bias,+res) -> C0 ; z=1 does [K/2,K) -> C1
__global__ void k_gemm_sk(const float* __restrict__ A, const float* __restrict__ Bw,
                          const float* __restrict__ bias, const float* __restrict__ res,
                          float* __restrict__ C0, float* __restrict__ C1, int N, int K)
{
    const int z = blockIdx.z;
    const int Kh = K >> 1;
    gemm_core(A + (size_t)z*Kh, K, Bw + (size_t)z*Kh*N,
              z ? nullptr : bias, z ? nullptr : res,
              z ? C1 : C0, N, Kh, 0, 0);
}

// ---------------- batched Q/K/V projection: grid.z = 2*n_eff+1 -------------
__global__ void k_kvq(const float* __restrict__ Wq, const float* __restrict__ bq,
                      const float* __restrict__ Wk, const float* __restrict__ bk,
                      const float* __restrict__ Wv, const float* __restrict__ bv,
                      int n_eff)
{
    int z = blockIdx.z;
    const float *A, *W, *bi; float* C;
    if (z == 2*n_eff) { A = g_x; W = Wq; bi = bq; C = g_q; }
    else {
        int isv = (z >= n_eff) ? 1 : 0;
        int j = isv ? z - n_eff : z;
        A = (j == 0) ? g_x : g_lo + (size_t)(j-1)*SBD;
        W = isv ? Wv : Wk;
        bi = isv ? bv : bk;
        C = (isv ? g_v : g_k) + (size_t)j*SBD;
    }
    gemm_core(A, Dm, W, bi, nullptr, C, Dm, Dm, 0, 0);
}

// ---------------- embedding + positional encoding ---------------------------
__global__ void k_embed(const int* __restrict__ src, const float* __restrict__ emb)
{
    int idx = blockIdx.x * 256 + threadIdx.x;       // over SBD
    int d = idx & (Dm-1);
    int r = idx >> 10;
    int b = r & 1, s = r >> 1;
    int tok = src[b*Sq + s];
    float v = emb[(size_t)tok*Dm + d] * 32.0f;      // sqrt(1024)
    int de = d & ~1;
    float ang = (float)s * expf((float)de * -0.008994473019508f); // -ln(1e4)/1024
    float pe = (d & 1) ? cosf(ang) : sinf(ang);
    g_x[idx] = v + pe;
}

// ---------------- scores: per (source j, head bh) NT-GEMM -------------------
__global__ void k_scores(int n_eff)
{
    __shared__ __align__(16) float Qs[2][16][LDK];
    __shared__ __align__(16) float Ks[2][16][LDK];
    const int tid = threadIdx.x;
    const int tx = tid & 15, ty = tid >> 4;
    const int arow = tid >> 2, acol = (tid & 3) << 2;
    const int z = blockIdx.z;                 // z = j*16 + bh
    const int bh = z & 15;
    const int b = bh >> 3, h = bh & 7;
    const int LDX = Bsz * Dm;                 // 2048
    const float* Aq = g_q + b*Dm + h*HDm;
    const float* Bk = g_k + (size_t)(z >> 4)*SBD + b*Dm + h*HDm;
    float* C = g_scores + (size_t)z * Sq * Sq;
    const int m0 = blockIdx.y << 6, n0 = blockIdx.x << 6;
    float acc[4][4];
#pragma unroll
    for (int i=0;i<4;i++)
#pragma unroll
        for (int j=0;j<4;j++) acc[i][j]=0.f;

    const float* Ap = Aq + (size_t)(m0 + arow) * LDX + acol;
    const float* Bp = Bk + (size_t)(n0 + arow) * LDX + acol;
    float4 qR, kR;

    qR = *(const float4*)(Ap);
    kR = *(const float4*)(Bp);
    STAGE_T(Qs, 0, qR); STAGE_T(Ks, 0, kR);
    __syncthreads();

    for (int kt = 1; kt < 8; kt++) {          // HD=128 -> 8 k-tiles
        qR = *(const float4*)(Ap + kt*16);
        kR = *(const float4*)(Bp + kt*16);
        const int cb = (kt-1)&1, nb = kt&1;
        MM16F(Qs[cb], Ks[cb]);
        STAGE_T(Qs, nb, qR); STAGE_T(Ks, nb, kR);
        __syncthreads();
    }
    MM16F(Qs[1], Ks[1]);

#pragma unroll
    for (int i=0;i<4;i++){
        int m = m0 + (ty<<2) + i;
#pragma unroll
        for (int j=0;j<4;j++){
            int nn = n0 + (tx<<2) + j;
            C[(size_t)m*Sq + nn] = acc[i][j] * ATT_SCALE;
        }
    }
}

// ------- softmax over keys x layer weight (dedup: src0 gets w0 + w_{n-1}) ---
__global__ void k_softmax(const float* __restrict__ lw, int n, int n_eff)
{
    int row  = blockIdx.x * 8 + (threadIdx.x >> 5);   // rows = n_eff*16*256
    int lane = threadIdx.x & 31;
    float* p = g_scores + (size_t)row * Sq;
    float x[8];
#pragma unroll
    for (int i=0;i<8;i++) x[i] = p[lane + (i<<5)];
    float mx = x[0];
#pragma unroll
    for (int i=1;i<8;i++) mx = fmaxf(mx, x[i]);
#pragma unroll
    for (int off=16;off>0;off>>=1) mx = fmaxf(mx, __shfl_xor_sync(0xffffffffu, mx, off));
    float sum = 0.f;
#pragma unroll
    for (int i=0;i<8;i++){ x[i] = expf(x[i]-mx); sum += x[i]; }
#pragma unroll
    for (int off=16;off>0;off>>=1) sum += __shfl_xor_sync(0xffffffffu, sum, off);
    int jj = row >> 12;                                // row / (16*256)
    float lm = -1e30f;
    for (int t=0;t<n;t++) lm = fmaxf(lm, lw[t]);
    float ls = 0.f;
    for (int t=0;t<n;t++) ls += expf(lw[t]-lm);
    float wj = expf(lw[jj]-lm) / ls;
    if (n > n_eff && jj == 0) wj += expf(lw[n-1]-lm) / ls;   // merged duplicate
    float sc = wj / sum;
#pragma unroll
    for (int i=0;i<8;i++) p[lane + (i<<5)] = x[i] * sc;
}

// ---------------- comb: per head, sum over sources j of attn_j @ v_j --------
__global__ void k_comb(int n_eff)
{
    __shared__ __align__(16) float As[2][16][LDK];
    __shared__ __align__(16) float Bs[2][16][LDK];
    const int tid = threadIdx.x;
    const int tx = tid & 15, ty = tid >> 4;
    const int arow = tid >> 2, acol = (tid & 3) << 2;
    const int brow = tid >> 4, bcol = (tid & 15) << 2;
    const int bh = blockIdx.z, b = bh >> 3, h = bh & 7;
    const int m0 = blockIdx.y << 6, n0 = blockIdx.x << 6;   // q tile, d tile
    float acc[4][4];
#pragma unroll
    for (int i=0;i<4;i++)
#pragma unroll
        for (int j=0;j<4;j++) acc[i][j]=0.f;

    for (int j=0;j<n_eff;j++){
        const float* Aj = g_scores + (size_t)(j*16 + bh) * Sq * Sq;   // [q][k] ld=256
        const float* Vj = g_v + (size_t)j*SBD + b*Dm + h*HDm;          // [k][d] ld=2048
        const float* Ap = Aj + (size_t)(m0 + arow) * Sq + acol;
        float4 aR, bR;
        aR = *(const float4*)(Ap);
        bR = *(const float4*)(Vj + (size_t)brow*2048 + n0 + bcol);
        STAGE_T(As, 0, aR); STAGE_K(Bs, 0, bR);
        __syncthreads();
        for (int kt = 1; kt < 16; kt++) {     // Sq=256 -> 16 k-tiles
            aR = *(const float4*)(Ap + kt*16);
            bR = *(const float4*)(Vj + (size_t)(kt*16+brow)*2048 + n0 + bcol);
            const int cb = (kt-1)&1, nb = kt&1;
            MM16F(As[cb], Bs[cb]);
            STAGE_T(As, nb, aR); STAGE_K(Bs, nb, bR);
            __syncthreads();
        }
        MM16F(As[1], Bs[1]);
        __syncthreads();                      // buffers reused by next source
    }

#pragma unroll
    for (int i=0;i<4;i++){
        int q = m0 + (ty<<2) + i;
        int r = q*Bsz + b;
#pragma unroll
        for (int j=0;j<4;j++){
            int d = h*HDm + n0 + (tx<<2) + j;
            g_comb[(size_t)r*Dm + d] = acc[i][j];
        }
    }
}

// ------- layernorm over D of (in [+ in2]), write out (and optional copy) ----
__global__ void k_ln(const float* __restrict__ in, const float* __restrict__ in2,
                     const float* __restrict__ g, const float* __restrict__ be,
                     float* __restrict__ out, float* __restrict__ out2)
{
    __shared__ float s1[8], s2[8];
    __shared__ float smean, srstd;
    int r = blockIdx.x, tid = threadIdx.x;
    int lane = tid & 31, wid = tid >> 5;
    const float* row  = in  + (size_t)r*Dm;
    const float* row2 = in2 ? in2 + (size_t)r*Dm : nullptr;
    float v[4], sum = 0.f, sq = 0.f;
#pragma unroll
    for (int i=0;i<4;i++){
        float t = row[tid + (i<<8)];
        if (row2) t += row2[tid + (i<<8)];
        v[i] = t; sum += t; sq += t*t;
    }
#pragma unroll
    for (int off=16;off>0;off>>=1){
        sum += __shfl_xor_sync(0xffffffffu, sum, off);
        sq  += __shfl_xor_sync(0xffffffffu, sq,  off);
    }
    if (lane == 0){ s1[wid] = sum; s2[wid] = sq; }
    __syncthreads();
    if (tid == 0){
        float a=0.f, c=0.f;
        for (int i=0;i<8;i++){ a += s1[i]; c += s2[i]; }
        float mean = a * (1.f/1024.f);
        float var  = c * (1.f/1024.f) - mean*mean;
        smean = mean; srstd = rsqrtf(var + 1e-5f);
    }
    __syncthreads();
    float mean = smean, rstd = srstd;
#pragma unroll
    for (int i=0;i<4;i++){
        int d = tid + (i<<8);
        float o = (v[i]-mean)*rstd*g[d] + be[d];
        out[(size_t)r*Dm + d] = o;
        if (out2) out2[(size_t)r*Dm + d] = o;
    }
}

// ---------------- SNN scan: one block per batch, 1024 threads ---------------
// current = cur + cur2 (two split-K partials)
__global__ void k_snn(const float* __restrict__ cur, const float* __restrict__ cur2,
                      float* __restrict__ sp)
{
    __shared__ float red[32];
    __shared__ float redt;
    int b = blockIdx.x, d = threadIdx.x;
    int lane = d & 31, wid = d >> 5;
    float mem = 0.f, thr = 1.0f;
    size_t i0 = (size_t)b*Dm + d;
    float nxt = cur[i0] + cur2[i0];                  // t = 0 row = (0*B+b)
    for (int t=0;t<Sq;t++){
        float cin = nxt;
        if (t+1 < Sq){
            size_t ix = (size_t)((t+1)*Bsz + b)*Dm + d;
            nxt = cur[ix] + cur2[ix];
        }
        float v = mem;
#pragma unroll
        for (int off=16;off>0;off>>=1) v += __shfl_xor_sync(0xffffffffu, v, off);
        if (lane == 0) red[wid] = v;
        __syncthreads();
        if (wid == 0){
            float u = red[lane];
#pragma unroll
            for (int off=16;off>0;off>>=1) u += __shfl_xor_sync(0xffffffffu, u, off);
            if (lane == 0) redt = u;
        }
        __syncthreads();
        float c = cin - 0.1f * redt;
        mem = 0.9f * mem + c;
        float s = (mem >= thr) ? 1.f : 0.f;
        mem -= s * thr;
        thr = 0.9f * thr + 0.1f * s;
        sp[(size_t)(t*Bsz + b)*Dm + d] = s;
    }
}

// ---------------- host orchestration ----------------------------------------
extern "C" void kernel_launch(void* const* d_in, const int* in_sizes, int n_in,
                              void* d_out, int out_size)
{
    const int*   src  = (const int*)  d_in[0];
    const float* emb  = (const float*)d_in[1];
    const float* Wq   = (const float*)d_in[2];
    const float* bq   = (const float*)d_in[3];
    const float* Wk   = (const float*)d_in[4];
    const float* bk   = (const float*)d_in[5];
    const float* Wv   = (const float*)d_in[6];
    const float* bv   = (const float*)d_in[7];
    const float* Wo   = (const float*)d_in[8];
    const float* bo   = (const float*)d_in[9];
    const float* layer_w = (const float*)d_in[10];
    const float* Wsnn = (const float*)d_in[11];
    const float* bsnn = (const float*)d_in[12];
    const float* W1   = (const float*)d_in[13];
    const float* b1   = (const float*)d_in[14];
    const float* W2   = (const float*)d_in[15];
    const float* b2   = (const float*)d_in[16];
    const float* g1   = (const float*)d_in[17];
    const float* be1  = (const float*)d_in[18];
    const float* g2   = (const float*)d_in[19];
    const float* be2  = (const float*)d_in[20];
    const float* Wout = (const float*)d_in[21];
    const float* bout = (const float*)d_in[22];
    float* out = (float*)d_out;

    float *px, *pcomb, *pres, *pp2, *psp, *ph, *plo;
    cudaGetSymbolAddress((void**)&px,    g_x);
    cudaGetSymbolAddress((void**)&pcomb, g_comb);
    cudaGetSymbolAddress((void**)&pres,  g_res);
    cudaGetSymbolAddress((void**)&pp2,   g_p2);
    cudaGetSymbolAddress((void**)&psp,   g_sp);
    cudaGetSymbolAddress((void**)&ph,    g_h);
    cudaGetSymbolAddress((void**)&plo,   g_lo);

    k_embed<<<SBD/256, 256>>>(src, emb);

    for (int l=0; l<Ll; l++){
        int n = l + 1;                      // true source count
        int n_eff = (l == 0) ? 1 : l;       // deduped (srcs[0]==srcs[l] for l>=1)
        const float* Wql = Wq + (size_t)l*Dm*Dm;
        const float* Wkl = Wk + (size_t)l*Dm*Dm;
        const float* Wvl = Wv + (size_t)l*Dm*Dm;

        // Q + n_eff*K + n_eff*V projections, batched over grid.z
        k_kvq<<<dim3(16,8,2*n_eff+1), 256>>>(Wql, bq + l*Dm, Wkl, bk + l*Dm,
                                             Wvl, bv + l*Dm, n_eff);
        // attention scores, per (source, head)
        k_scores<<<dim3(4,4,n_eff*16), 256>>>(n_eff);
        // softmax over keys x layer-weight softmax (merged dup weight)
        k_softmax<<<n_eff*16*Sq/8, 256>>>(layer_w + l*(Ll+1), n, n_eff);
        // combine over (k, source)
        k_comb<<<dim3(2,4,16), 256>>>(n_eff);
        // output projection + residual, split-K=2 partials
        k_gemm_sk<<<dim3(16,8,2), 256>>>(pcomb, Wo + (size_t)l*Dm*Dm, bo + l*Dm,
                                         px, pres, pp2, Dm, Dm);
        // LN1 (sums both partials) -> new x
        k_ln<<<SB, 256>>>(pres, pp2, g1 + l*Dm, be1 + l*Dm, px, (float*)nullptr);
        // SNN input current, split-K=2 partials
        k_gemm_sk<<<dim3(16,8,2), 256>>>(px, Wsnn + (size_t)l*Dm*Dm, bsnn + l*Dm,
                                         (const float*)nullptr, ph, pp2, Dm, Dm);
        // membrane scan -> spikes
        k_snn<<<Bsz, 1024>>>(ph, pp2, psp);
        // FF1 (relu)
        k_gemm<<<dim3(32,8), 256>>>(psp, W1 + (size_t)l*Dm*FFd, b1 + l*FFd,
                                    (const float*)nullptr, ph, FFd, Dm, 1, 0);
        // FF2 + residual, split-K=2 partials
        k_gemm_sk<<<dim3(16,8,2), 256>>>(ph, W2 + (size_t)l*FFd*Dm, b2 + l*Dm,
                                         px, pres, pp2, Dm, FFd);
        // LN2 (sums partials) -> new x, also store as this layer's output
        k_ln<<<SB, 256>>>(pres, pp2, g2 + l*Dm, be2 + l*Dm, px, plo + (size_t)l*SBD);
    }

    // final logits with transposed store into [B,S,V]
    k_gemm<<<dim3((Vv+63)/64, 8), 256>>>(px, Wout, bout, (const float*)nullptr,
                                         out, Vv, Dm, 0, 1);
}